// round 13
// baseline (speedup 1.0000x reference)
#include <cuda_runtime.h>

// Problem constants (fixed by the dataset).
#define N_NEURONS 2000000u
#define N_EDGES   16000000u

// Smem per-lane-column bit filter (layer 3 + fallback): 128 words/column.
#define CWORDS 128
#define FILT_WORDS (CWORDS * 32)          // 4096 words = 16KB

// Register dual-Bloom (layer 2): two 64-bit words, two mult hashes.
#define M0 2654435761u
#define M1 2246822519u
#define REG_FILT_MAX 24                   // beyond this, use smem fallback

#define TCAP (1 << 20)                    // touched-list capacity
#define ACAP (1 << 20)                    // active-list capacity

// Scratch state (allocation-free __device__ globals; zero at load, and every
// launch restores the pristine state => deterministic graph replays).
__device__ float              g_x[N_NEURONS];
__device__ float              g_out[N_NEURONS];
__device__ unsigned           g_act[ACAP];
__device__ unsigned           g_acnt;
__device__ unsigned           g_touched[TCAP];
__device__ unsigned           g_tcnt[3];
__device__ unsigned           g_done[4];   // last-block tickets, self-resetting
__device__ unsigned long long g_f2a, g_f2b; // register-filter words (rebuilt each replay)
__device__ unsigned           g_f2_fb;      // 1 => layer-2 must use smem fallback

// Scatter with touched-list registration. Exactly one adder per cell observes
// old == 0.0f; duplicate touched entries are defused by atomicExch in the tail.
__device__ __forceinline__ void scatter_edge(int d, float val, int r) {
    if (val == 0.0f) return;
    float old = atomicAdd(&g_out[d], val);
    if (old == 0.0f) {
        unsigned p = atomicAdd(&g_tcnt[r], 1u);
        if (p < TCAP) g_touched[p] = (unsigned)d;
    }
}

// Last-block election: true for every thread of the block that arrives last.
__device__ __forceinline__ bool elect_last_block(int which) {
    __shared__ unsigned s_last;
    __threadfence();
    __syncthreads();
    if (threadIdx.x == 0) {
        unsigned t = atomicAdd(&g_done[which], 1u);
        s_last = (t == gridDim.x - 1) ? 1u : 0u;
        if (s_last) g_done[which] = 0u;   // self-reset for next replay
    }
    __syncthreads();
    if (s_last) { __threadfence(); return true; }
    return false;
}

// Update tail: x += relu(out) over touched cells, out -> 0, new actives
// appended. atomicExch makes duplicate touched entries process exactly once.
__device__ void update_tail(int r, int tid, int nthr) {
    unsigned tc = g_tcnt[r];
    if (tc <= TCAP) {
        for (unsigned t = tid; t < tc; t += nthr) {
            unsigned i = g_touched[t];
            float v = atomicExch(&g_out[i], 0.0f);
            if (v > 0.0f) {
                float xo = g_x[i];
                g_x[i] = xo + v;
                if (xo == 0.0f) {
                    unsigned p = atomicAdd(&g_acnt, 1u);
                    if (p < ACAP) g_act[p] = i;
                }
            }
        }
    } else {                               // overflow fallback: full sweep
        for (unsigned i = tid; i < N_NEURONS; i += nthr) {
            float v = atomicExch(&g_out[i], 0.0f);
            if (v > 0.0f) {
                float xo = g_x[i];
                g_x[i] = xo + v;
                if (xo == 0.0f) {
                    unsigned p = atomicAdd(&g_acnt, 1u);
                    if (p < ACAP) g_act[p] = i;
                }
            }
        }
    }
}

// ---------------------------------------------------------------------------
// Start: seed x[0]=1, active={0}, counters=0.
// ---------------------------------------------------------------------------
__global__ void k_start() {
    g_x[0] = 1.0f;
    g_act[0] = 0u;
    g_acnt = 1u;
    g_tcnt[0] = 0u; g_tcnt[1] = 0u; g_tcnt[2] = 0u;
    g_out[0] = 0.0f;
}

// ---------------------------------------------------------------------------
// Layer 0: active set is exactly {0, value 1.0} -> compare only. Tail: round-0
// update, then build the layer-2 register filter from the new active set.
// ---------------------------------------------------------------------------
__global__ void __launch_bounds__(256, 8)
k_edge_first(const int* __restrict__ src, const int* __restrict__ dst,
             const int* __restrict__ widx, const float* __restrict__ weights) {
    unsigned stride = gridDim.x * blockDim.x * 8u;
    for (unsigned i = (blockIdx.x * blockDim.x + threadIdx.x) * 8u; i < N_EDGES; i += stride) {
        int4 a = __ldcs(reinterpret_cast<const int4*>(src + i));
        int4 b = __ldcs(reinterpret_cast<const int4*>(src + i + 4));
        int s[8] = {a.x, a.y, a.z, a.w, b.x, b.y, b.z, b.w};
        #pragma unroll
        for (int j = 0; j < 8; ++j) {
            if (s[j] == 0) {
                unsigned e = i + j;
                scatter_edge(__ldg(dst + e), __ldg(weights + __ldg(widx + e)), 0);
            }
        }
    }
    if (elect_last_block(0)) {
        update_tail(0, threadIdx.x, blockDim.x);
        __syncthreads();                          // actives final (same block)
        if (threadIdx.x == 0) {
            unsigned cnt = g_acnt;
            if (cnt <= REG_FILT_MAX) {
                unsigned long long f0 = 0ull, f1 = 0ull;
                for (unsigned t = 0; t < cnt; ++t) {
                    unsigned k = g_act[t];
                    f0 |= 1ull << ((k * M0) >> 26);
                    f1 |= 1ull << ((k * M1) >> 26);
                }
                g_f2a = f0; g_f2b = f1; g_f2_fb = 0u;
            } else {
                g_f2_fb = 1u;                     // smem fallback path
            }
        }
    }
}

// ---------------------------------------------------------------------------
// Layer 1->2: register dual-Bloom, pure ALU per edge (no LDS, no MIO).
// pass => exact g_x gather (correct even on the ~2-4% false positives).
// Branch-free hitmask: one branch per 8 edges. Smem-filter fallback if the
// active set was too big for the register filter.
// ---------------------------------------------------------------------------
__global__ void __launch_bounds__(256, 8)
k_edge_f2(const int* __restrict__ src, const int* __restrict__ dst,
          const int* __restrict__ widx, const float* __restrict__ weights) {
    __shared__ unsigned sfilt[FILT_WORDS];
    bool fb = (g_f2_fb != 0u);

    if (fb) {   // build smem filter (rare path; same as layer-3 kernel)
        for (int t = threadIdx.x; t < FILT_WORDS; t += blockDim.x) sfilt[t] = 0u;
        __syncthreads();
        unsigned cnt = g_acnt; if (cnt > ACAP) cnt = ACAP;
        for (unsigned t = threadIdx.x; t < cnt * 32u; t += blockDim.x) {
            unsigned key = g_act[t >> 5];
            atomicOr(&sfilt[((key & 127u) << 5) + (t & 31u)], 1u << ((key >> 7) & 31u));
        }
        __syncthreads();
    }

    const unsigned long long F0 = g_f2a, F1 = g_f2b;
    const unsigned* mycol = sfilt + (threadIdx.x & 31u);
    unsigned stride = gridDim.x * blockDim.x * 8u;

    for (unsigned i = (blockIdx.x * blockDim.x + threadIdx.x) * 8u; i < N_EDGES; i += stride) {
        int4 a = __ldcs(reinterpret_cast<const int4*>(src + i));
        int4 b = __ldcs(reinterpret_cast<const int4*>(src + i + 4));
        int s[8] = {a.x, a.y, a.z, a.w, b.x, b.y, b.z, b.w};
        unsigned hm = 0u;
        if (!fb) {
            #pragma unroll
            for (int j = 0; j < 8; ++j) {
                unsigned sj = (unsigned)s[j];
                unsigned p = (unsigned)((F0 >> ((sj * M0) >> 26)) &
                                        (F1 >> ((sj * M1) >> 26))) & 1u;
                hm |= p << j;
            }
        } else {
            #pragma unroll
            for (int j = 0; j < 8; ++j) {
                unsigned sj = (unsigned)s[j];
                unsigned word = mycol[(sj & 127u) << 5];
                hm |= ((word >> ((sj >> 7) & 31u)) & 1u) << j;
            }
        }
        if (hm) {
            #pragma unroll
            for (int j = 0; j < 8; ++j) {
                if (hm & (1u << j)) {
                    unsigned sj = (unsigned)s[j];
                    float xv = g_x[sj];              // exact; 0.0 on FP
                    if (xv != 0.0f) {
                        unsigned e = i + j;
                        scatter_edge(__ldg(dst + e), xv * __ldg(weights + __ldg(widx + e)), 1);
                    }
                }
            }
        }
    }
    if (elect_last_block(1)) update_tail(1, threadIdx.x, blockDim.x);
}

// ---------------------------------------------------------------------------
// Layer 2->3: smem bit filter (active set ~81 too big for registers), but
// branch-free hitmask — one branch per 8 edges instead of 8.
// ---------------------------------------------------------------------------
__global__ void __launch_bounds__(256, 8)
k_edge_f3(const int* __restrict__ src, const int* __restrict__ dst,
          const int* __restrict__ widx, const float* __restrict__ weights) {
    __shared__ unsigned sfilt[FILT_WORDS];

    for (int t = threadIdx.x; t < FILT_WORDS; t += blockDim.x) sfilt[t] = 0u;
    __syncthreads();
    unsigned cnt = g_acnt; if (cnt > ACAP) cnt = ACAP;
    for (unsigned t = threadIdx.x; t < cnt * 32u; t += blockDim.x) {
        unsigned key = g_act[t >> 5];
        atomicOr(&sfilt[((key & 127u) << 5) + (t & 31u)], 1u << ((key >> 7) & 31u));
    }
    __syncthreads();

    const unsigned* mycol = sfilt + (threadIdx.x & 31u);
    unsigned stride = gridDim.x * blockDim.x * 8u;

    for (unsigned i = (blockIdx.x * blockDim.x + threadIdx.x) * 8u; i < N_EDGES; i += stride) {
        int4 a = __ldcs(reinterpret_cast<const int4*>(src + i));
        int4 b = __ldcs(reinterpret_cast<const int4*>(src + i + 4));
        int s[8] = {a.x, a.y, a.z, a.w, b.x, b.y, b.z, b.w};
        unsigned hm = 0u;
        #pragma unroll
        for (int j = 0; j < 8; ++j) {
            unsigned sj = (unsigned)s[j];
            unsigned word = mycol[(sj & 127u) << 5];     // bank == lane
            hm |= ((word >> ((sj >> 7) & 31u)) & 1u) << j;
        }
        if (hm) {
            #pragma unroll
            for (int j = 0; j < 8; ++j) {
                if (hm & (1u << j)) {
                    unsigned sj = (unsigned)s[j];
                    float xv = g_x[sj];                  // exact; 0.0 on FP
                    if (xv != 0.0f) {
                        unsigned e = i + j;
                        scatter_edge(__ldg(dst + e), xv * __ldg(weights + __ldg(widx + e)), 2);
                    }
                }
            }
        }
    }
    if (elect_last_block(2)) update_tail(2, threadIdx.x, blockDim.x);
}

// ---------------------------------------------------------------------------
// Layer 3: only out[0] matters -> scan dst==0, gather x[src] on the ~8 hits.
// Tail writes the final result and restores pristine global state.
// ---------------------------------------------------------------------------
__global__ void __launch_bounds__(256, 8)
k_edge_last(const int* __restrict__ src, const int* __restrict__ dst,
            const int* __restrict__ widx, const float* __restrict__ weights,
            float* __restrict__ out) {
    unsigned stride = gridDim.x * blockDim.x * 8u;
    for (unsigned i = (blockIdx.x * blockDim.x + threadIdx.x) * 8u; i < N_EDGES; i += stride) {
        int4 a = __ldcs(reinterpret_cast<const int4*>(dst + i));
        int4 b = __ldcs(reinterpret_cast<const int4*>(dst + i + 4));
        int d[8] = {a.x, a.y, a.z, a.w, b.x, b.y, b.z, b.w};
        #pragma unroll
        for (int j = 0; j < 8; ++j) {
            if (d[j] == 0) {
                unsigned e = i + j;
                atomicAdd(&g_out[0], g_x[__ldg(src + e)] * __ldg(weights + __ldg(widx + e)));
            }
        }
    }
    if (elect_last_block(3)) {
        int tid = threadIdx.x, nthr = blockDim.x;
        if (tid == 0) out[0] = g_x[0] + fmaxf(g_out[0], 0.0f);
        // Cleanup: zero every nonzero g_x cell (active list), zero g_out[0].
        unsigned ac = g_acnt;
        if (ac <= ACAP) {
            for (unsigned t = tid; t < ac; t += nthr) g_x[g_act[t]] = 0.0f;
        } else {
            for (unsigned i = tid; i < N_NEURONS; i += nthr) g_x[i] = 0.0f;
        }
        if (tid == 0) g_out[0] = 0.0f;
    }
}

// ---------------------------------------------------------------------------
// Launch sequence (graph-capturable: kernel launches only). Per-layer edge
// pointers pre-offset on the host so device indexing stays 32-bit.
// Inputs: [0]=weights f32[1024], [1]=src i32[4*16M], [2]=dst i32[4*16M],
// [3]=widx i32[4*16M]. Output: f32[1].
// ---------------------------------------------------------------------------
extern "C" void kernel_launch(void* const* d_in, const int* in_sizes, int n_in,
                              void* d_out, int out_size) {
    const float* weights = (const float*)d_in[0];
    const int*   src     = (const int*)d_in[1];
    const int*   dst     = (const int*)d_in[2];
    const int*   widx    = (const int*)d_in[3];
    float*       out     = (float*)d_out;

    const int EB = 1184, ET = 256;   // 8 CTAs/SM on 148 SMs
    const size_t E = (size_t)N_EDGES;

    k_start<<<1, 1>>>();
    k_edge_first<<<EB, ET>>>(src, dst, widx, weights);
    k_edge_f2<<<EB, ET>>>(src + E,   dst + E,   widx + E,   weights);
    k_edge_f3<<<EB, ET>>>(src + 2*E, dst + 2*E, widx + 2*E, weights);
    k_edge_last<<<EB, ET>>>(src + 3*E, dst + 3*E, widx + 3*E, weights, out);
}

// round 14
// speedup vs baseline: 1.0297x; 1.0297x over previous
#include <cuda_runtime.h>

// Problem constants (fixed by the dataset).
#define N_NEURONS 2000000u
#define N_EDGES   16000000u

// Byte-map filter: sbyte[sj & (BSIZE-1)] != 0 <=> candidate active.
// Query = AND + LDS.U8 + ISETP: ~2 extra instructions per edge vs a plain
// compare. FP rate = actives/BSIZE (~0.5%); FPs are resolved by an exact
// g_x gather, so correctness never depends on the filter.
#define BSIZE 16384u                      // 16KB smem => 8 CTAs/SM

#define TCAP (1 << 20)                    // touched-list capacity
#define ACAP (1 << 20)                    // active-list capacity

// Scratch state (allocation-free __device__ globals; zero at load, and every
// launch restores the pristine state => deterministic graph replays).
__device__ float    g_x[N_NEURONS];
__device__ float    g_out[N_NEURONS];
__device__ unsigned g_act[ACAP];
__device__ unsigned g_acnt;
__device__ unsigned g_touched[TCAP];
__device__ unsigned g_tcnt[3];
__device__ unsigned g_done[4];            // last-block tickets, self-resetting

// Scatter with touched-list registration. Exactly one adder per cell observes
// old == 0.0f; duplicate touched entries are defused by atomicExch in the tail.
__device__ __forceinline__ void scatter_edge(int d, float val, int r) {
    if (val == 0.0f) return;
    float old = atomicAdd(&g_out[d], val);
    if (old == 0.0f) {
        unsigned p = atomicAdd(&g_tcnt[r], 1u);
        if (p < TCAP) g_touched[p] = (unsigned)d;
    }
}

// Last-block election: true for every thread of the block that arrives last.
__device__ __forceinline__ bool elect_last_block(int which) {
    __shared__ unsigned s_last;
    __threadfence();
    __syncthreads();
    if (threadIdx.x == 0) {
        unsigned t = atomicAdd(&g_done[which], 1u);
        s_last = (t == gridDim.x - 1) ? 1u : 0u;
        if (s_last) g_done[which] = 0u;   // self-reset for next replay
    }
    __syncthreads();
    if (s_last) { __threadfence(); return true; }
    return false;
}

// Update tail: x += relu(out) over touched cells, out -> 0, new actives
// appended. atomicExch makes duplicate touched entries process exactly once.
__device__ void update_tail(int r, int tid, int nthr) {
    unsigned tc = g_tcnt[r];
    if (tc <= TCAP) {
        for (unsigned t = tid; t < tc; t += nthr) {
            unsigned i = g_touched[t];
            float v = atomicExch(&g_out[i], 0.0f);
            if (v > 0.0f) {
                float xo = g_x[i];
                g_x[i] = xo + v;
                if (xo == 0.0f) {
                    unsigned p = atomicAdd(&g_acnt, 1u);
                    if (p < ACAP) g_act[p] = i;
                }
            }
        }
    } else {                               // overflow fallback: full sweep
        for (unsigned i = tid; i < N_NEURONS; i += nthr) {
            float v = atomicExch(&g_out[i], 0.0f);
            if (v > 0.0f) {
                float xo = g_x[i];
                g_x[i] = xo + v;
                if (xo == 0.0f) {
                    unsigned p = atomicAdd(&g_acnt, 1u);
                    if (p < ACAP) g_act[p] = i;
                }
            }
        }
    }
}

// ---------------------------------------------------------------------------
// Start: seed x[0]=1, active={0}, counters=0.
// ---------------------------------------------------------------------------
__global__ void k_start() {
    g_x[0] = 1.0f;
    g_act[0] = 0u;
    g_acnt = 1u;
    g_tcnt[0] = 0u; g_tcnt[1] = 0u; g_tcnt[2] = 0u;
    g_out[0] = 0.0f;
}

// ---------------------------------------------------------------------------
// Layer 0: active set is exactly {0, value 1.0} -> compare only.
// ---------------------------------------------------------------------------
__global__ void __launch_bounds__(256, 8)
k_edge_first(const int* __restrict__ src, const int* __restrict__ dst,
             const int* __restrict__ widx, const float* __restrict__ weights) {
    unsigned stride = gridDim.x * blockDim.x * 8u;
    for (unsigned i = (blockIdx.x * blockDim.x + threadIdx.x) * 8u; i < N_EDGES; i += stride) {
        int4 a = __ldcs(reinterpret_cast<const int4*>(src + i));
        int4 b = __ldcs(reinterpret_cast<const int4*>(src + i + 4));
        int s[8] = {a.x, a.y, a.z, a.w, b.x, b.y, b.z, b.w};
        #pragma unroll
        for (int j = 0; j < 8; ++j) {
            if (s[j] == 0) {
                unsigned e = i + j;
                scatter_edge(__ldg(dst + e), __ldg(weights + __ldg(widx + e)), 0);
            }
        }
    }
    if (elect_last_block(0)) update_tail(0, threadIdx.x, blockDim.x);
}

// ---------------------------------------------------------------------------
// Layers 1,2: byte-map filter. Per edge: AND + LDS.U8 + predicate — the
// cheapest possible membership approximation. On pass (true hit or ~0.5%
// false positive) gather g_x[sj], which is exact. Build = one byte store per
// active key (same-value races benign). No false negatives possible.
// ---------------------------------------------------------------------------
__global__ void __launch_bounds__(256, 8)
k_edge_bfilt(const int* __restrict__ src, const int* __restrict__ dst,
             const int* __restrict__ widx, const float* __restrict__ weights,
             int round) {
    __shared__ unsigned char sbyte[BSIZE];

    // Zero the byte map (16KB) with wide stores.
    {
        uint4* p = reinterpret_cast<uint4*>(sbyte);
        const uint4 z = make_uint4(0u, 0u, 0u, 0u);
        for (unsigned t = threadIdx.x; t < BSIZE / 16u; t += blockDim.x) p[t] = z;
    }
    __syncthreads();

    // Mark active keys.
    unsigned cnt = g_acnt;
    if (cnt > ACAP) cnt = ACAP;
    for (unsigned t = threadIdx.x; t < cnt; t += blockDim.x)
        sbyte[g_act[t] & (BSIZE - 1u)] = 1u;
    __syncthreads();

    unsigned stride = gridDim.x * blockDim.x * 8u;
    for (unsigned i = (blockIdx.x * blockDim.x + threadIdx.x) * 8u; i < N_EDGES; i += stride) {
        int4 a = __ldcs(reinterpret_cast<const int4*>(src + i));
        int4 b = __ldcs(reinterpret_cast<const int4*>(src + i + 4));
        int s[8] = {a.x, a.y, a.z, a.w, b.x, b.y, b.z, b.w};
        #pragma unroll
        for (int j = 0; j < 8; ++j) {
            unsigned sj = (unsigned)s[j];
            if (sbyte[sj & (BSIZE - 1u)]) {
                float xv = g_x[sj];                  // exact; 0.0 on FP
                if (xv != 0.0f) {
                    unsigned e = i + j;
                    scatter_edge(__ldg(dst + e), xv * __ldg(weights + __ldg(widx + e)), round);
                }
            }
        }
    }
    if (elect_last_block(round)) update_tail(round, threadIdx.x, blockDim.x);
}

// ---------------------------------------------------------------------------
// Layer 3: only out[0] matters -> scan dst==0, gather x[src] on the ~8 hits.
// Tail writes the final result and restores pristine global state.
// ---------------------------------------------------------------------------
__global__ void __launch_bounds__(256, 8)
k_edge_last(const int* __restrict__ src, const int* __restrict__ dst,
            const int* __restrict__ widx, const float* __restrict__ weights,
            float* __restrict__ out) {
    unsigned stride = gridDim.x * blockDim.x * 8u;
    for (unsigned i = (blockIdx.x * blockDim.x + threadIdx.x) * 8u; i < N_EDGES; i += stride) {
        int4 a = __ldcs(reinterpret_cast<const int4*>(dst + i));
        int4 b = __ldcs(reinterpret_cast<const int4*>(dst + i + 4));
        int d[8] = {a.x, a.y, a.z, a.w, b.x, b.y, b.z, b.w};
        #pragma unroll
        for (int j = 0; j < 8; ++j) {
            if (d[j] == 0) {
                unsigned e = i + j;
                atomicAdd(&g_out[0], g_x[__ldg(src + e)] * __ldg(weights + __ldg(widx + e)));
            }
        }
    }
    if (elect_last_block(3)) {
        int tid = threadIdx.x, nthr = blockDim.x;
        if (tid == 0) out[0] = g_x[0] + fmaxf(g_out[0], 0.0f);
        // Cleanup: zero every nonzero g_x cell (active list), zero g_out[0].
        unsigned ac = g_acnt;
        if (ac <= ACAP) {
            for (unsigned t = tid; t < ac; t += nthr) g_x[g_act[t]] = 0.0f;
        } else {
            for (unsigned i = tid; i < N_NEURONS; i += nthr) g_x[i] = 0.0f;
        }
        if (tid == 0) g_out[0] = 0.0f;
    }
}

// ---------------------------------------------------------------------------
// Launch sequence (graph-capturable: kernel launches only). Per-layer edge
// pointers pre-offset on the host so device indexing stays 32-bit.
// Inputs: [0]=weights f32[1024], [1]=src i32[4*16M], [2]=dst i32[4*16M],
// [3]=widx i32[4*16M]. Output: f32[1].
// ---------------------------------------------------------------------------
extern "C" void kernel_launch(void* const* d_in, const int* in_sizes, int n_in,
                              void* d_out, int out_size) {
    const float* weights = (const float*)d_in[0];
    const int*   src     = (const int*)d_in[1];
    const int*   dst     = (const int*)d_in[2];
    const int*   widx    = (const int*)d_in[3];
    float*       out     = (float*)d_out;

    const int EB = 1184, ET = 256;   // 8 CTAs/SM on 148 SMs
    const size_t E = (size_t)N_EDGES;

    k_start<<<1, 1>>>();
    k_edge_first<<<EB, ET>>>(src, dst, widx, weights);
    k_edge_bfilt<<<EB, ET>>>(src + E,   dst + E,   widx + E,   weights, 1);
    k_edge_bfilt<<<EB, ET>>>(src + 2*E, dst + 2*E, widx + 2*E, weights, 2);
    k_edge_last<<<EB, ET>>>(src + 3*E, dst + 3*E, widx + 3*E, weights, out);
}